// round 14
// baseline (speedup 1.0000x reference)
#include <cuda_runtime.h>
#include <cuda_bf16.h>
#include <cstdint>

// Problem constants
#define B_    256
#define D_    2048
#define N0_   7936
#define NTOT  8192
#define KSEL  128
#define NSEL  144          // selection margin: collect >= 144 noisy-smallest
#define CAND_MAX 256
#define EPS_F 1e-12f
#define KEY_OFF 0x45800    // (bits of 4096.0f) >> 12

// ---------------- scratch ----------------------------------------------------
__device__ float    g_ftq[B_ * D_];             // f_t^2 (fp32)
__device__ uint16_t g_ftq_bf[B_ * D_];          // f_t^2 bf16
__device__ uint16_t g_gal_bf[(size_t)N0_ * D_]; // gallery bf16
__device__ float    g_qns[B_];
__device__ float    g_qnt[B_];
__device__ float    g_gn[NTOT];
__device__ float    g_selfd2[B_];               // reference-noise-scale self d2
__device__ uint16_t g_key[(size_t)B_ * NTOT];   // quantized d2 keys
__device__ int      g_cand[B_ * CAND_MAX];
__device__ int      g_candn[B_];
__device__ float    g_rowmain[B_];
__device__ float    g_rowextra[B_];

// ---------------- PTX helpers -------------------------------------------------
__device__ __forceinline__ uint32_t smem_to_u32(const void* p) {
    uint32_t a;
    asm("{ .reg .u64 t; cvta.to.shared.u64 t, %1; cvt.u32.u64 %0, t; }" : "=r"(a) : "l"(p));
    return a;
}

#define LDSM_X4(R, ADDR) \
    asm volatile("ldmatrix.sync.aligned.m8n8.x4.shared.b16 {%0,%1,%2,%3}, [%4];" \
        : "=r"((R)[0]), "=r"((R)[1]), "=r"((R)[2]), "=r"((R)[3]) : "r"(ADDR))

#define MMA_BF16(D, A, B0, B1) \
    asm volatile("mma.sync.aligned.m16n8k16.row.col.f32.bf16.bf16.f32 " \
        "{%0,%1,%2,%3}, {%4,%5,%6,%7}, {%8,%9}, {%0,%1,%2,%3};" \
        : "+f"((D)[0]), "+f"((D)[1]), "+f"((D)[2]), "+f"((D)[3]) \
        : "r"((A)[0]), "r"((A)[1]), "r"((A)[2]), "r"((A)[3]), "r"(B0), "r"(B1))

#define CP_ASYNC16(dst, src) \
    asm volatile("cp.async.cg.shared.global [%0], [%1], 16;" :: "r"(dst), "l"(src))
#define CP_COMMIT() asm volatile("cp.async.commit_group;" ::: "memory")
#define CP_WAIT2()  asm volatile("cp.async.wait_group 2;" ::: "memory")

__device__ __forceinline__ float blockReduceSum(float v) {
    int lane = threadIdx.x & 31, wid = threadIdx.x >> 5;
#pragma unroll
    for (int o = 16; o; o >>= 1) v += __shfl_down_sync(0xffffffffu, v, o);
    __shared__ float sh[32];
    if (lane == 0) sh[wid] = v;
    __syncthreads();
    int nw = (blockDim.x + 31) >> 5;
    v = (threadIdx.x < nw) ? sh[threadIdx.x] : 0.f;
    if (wid == 0) {
#pragma unroll
        for (int o = 16; o; o >>= 1) v += __shfl_down_sync(0xffffffffu, v, o);
    }
    return v;
}

__device__ __forceinline__ uint32_t pack_bf2(float a, float b) {
    return (uint32_t)__bfloat16_as_ushort(__float2bfloat16(a)) |
           ((uint32_t)__bfloat16_as_ushort(__float2bfloat16(b)) << 16);
}

// ---------------- kernel 1: unified prep --------------------------------------
// blocks [0, B_)            : teacher rows (ftq fp32/bf16, qnt, gn, selfd2)
// blocks [B_, B_+N0_)       : gallery rows (norm + bf16 copy)
// blocks [B_+N0_, +B_)      : student rows (qns only; squares recomputed inline
//                             downstream, bit-identical)
__global__ void __launch_bounds__(256) prep_kernel(const float* __restrict__ f_s,
                                                   const float* __restrict__ f_t,
                                                   const float* __restrict__ gallery) {
    __shared__ __align__(16) float row[D_];
    const int bid = blockIdx.x;
    const int tid = threadIdx.x;

    if (bid < B_) {
        // ---- teacher row ----
        const float4* src = (const float4*)(f_t + (size_t)bid * D_);
        float4* dst = (float4*)(g_ftq + (size_t)bid * D_);
        uint4* dbf = (uint4*)(g_ftq_bf + (size_t)bid * D_);
        const int i = tid * 2;
        float4 v0 = src[i], v1 = src[i + 1];
        float4 s0 = make_float4(v0.x * v0.x, v0.y * v0.y, v0.z * v0.z, v0.w * v0.w);
        float4 s1 = make_float4(v1.x * v1.x, v1.y * v1.y, v1.z * v1.z, v1.w * v1.w);
        dst[i] = s0; dst[i + 1] = s1;
        ((float4*)row)[i] = s0; ((float4*)row)[i + 1] = s1;
        uint4 bf;
        bf.x = pack_bf2(s0.x, s0.y); bf.y = pack_bf2(s0.z, s0.w);
        bf.z = pack_bf2(s1.x, s1.y); bf.w = pack_bf2(s1.z, s1.w);
        dbf[tid] = bf;

        // qnt: sq_kernel's exact accumulation order
        float p = 0.f;
        p += s0.x * s0.x + s0.y * s0.y + s0.z * s0.z + s0.w * s0.w;
        p += s1.x * s1.x + s1.y * s1.y + s1.z * s1.z + s1.w * s1.w;
        const float qnt_tot = blockReduceSum(p);
        if (tid == 0) g_qnt[bid] = qnt_tot;
        __syncthreads();

        // gn: galnorm order (u-strided float4s)
        float pg = 0.f;
#pragma unroll
        for (int u = 0; u < 2; u++) {
            float4 s = ((const float4*)row)[tid + u * 256];
            pg += s.x * s.x + s.y * s.y + s.z * s.z + s.w * s.w;
        }
        const float gn_tot = blockReduceSum(pg);
        if (tid == 0) {
            g_gn[N0_ + bid] = gn_tot;
            // PURE SEQUENTIAL fp32 FMA chain (reference-noise-scale selfd2)
            float acc = 0.f;
#pragma unroll 16
            for (int k = 0; k < D_; k++) acc = fmaf(row[k], row[k], acc);
            const float t = qnt_tot + gn_tot;
            g_selfd2[bid] = fmaxf(fmaf(-2.f, acc, t), EPS_F);
        }
    } else if (bid < B_ + N0_) {
        // ---- gallery row ----
        const int n = bid - B_;
        const float4* g = (const float4*)(gallery + (size_t)n * D_);
        uint4* dbf = (uint4*)(g_gal_bf + (size_t)n * D_);
        float p = 0.f;
        float4 v0 = g[tid * 2], v1 = g[tid * 2 + 1];
        p += v0.x * v0.x + v0.y * v0.y + v0.z * v0.z + v0.w * v0.w;
        p += v1.x * v1.x + v1.y * v1.y + v1.z * v1.z + v1.w * v1.w;
        uint4 bf;
        bf.x = pack_bf2(v0.x, v0.y); bf.y = pack_bf2(v0.z, v0.w);
        bf.z = pack_bf2(v1.x, v1.y); bf.w = pack_bf2(v1.z, v1.w);
        dbf[tid] = bf;
        float tot = blockReduceSum(p);
        if (tid == 0) g_gn[n] = tot;
    } else {
        // ---- student row: qns only ----
        const int r = bid - B_ - N0_;
        const float4* src = (const float4*)(f_s + (size_t)r * D_);
        float p = 0.f;
#pragma unroll
        for (int u = 0; u < 2; u++) {
            float4 v = src[tid + u * 256];
            float4 s = make_float4(v.x * v.x, v.y * v.y, v.z * v.z, v.w * v.w);
            p += s.x * s.x + s.y * s.y + s.z * s.z + s.w * s.w;
        }
        float tot = blockReduceSum(p);
        if (tid == 0) g_qns[r] = tot;
    }
}

// ---------------- kernel 2: bf16 mma.sync GEMM -> quantized keys --------------
#define KC 64
#define NSTAGE 4
#define STAGE_B 32768
#define GEMM_SMEM (NSTAGE * STAGE_B)

__global__ void __launch_bounds__(256) bf16_gemm_kernel() {
    extern __shared__ __align__(16) char smem[];
    const int tid = threadIdx.x;
    const int ntile = blockIdx.x;    // 0..63
    const int mtile = blockIdx.y;    // 0..1

    const int r  = tid >> 1;
    const int h  = tid & 1;
    const uint16_t* aptr = g_ftq_bf + (size_t)(mtile * 128 + r) * D_ + h * 32;
    const int grow = ntile * 128 + r;
    const uint16_t* bptr = ((grow < N0_) ? (g_gal_bf + (size_t)grow * D_)
                                         : (g_ftq_bf + (size_t)(grow - N0_) * D_)) + h * 32;
    const uint32_t smem_u32 = smem_to_u32(smem);
    const uint32_t st_row = (uint32_t)r * 128u;
    uint32_t dsw[4];
#pragma unroll
    for (int u = 0; u < 4; u++) dsw[u] = (uint32_t)(((h * 4 + u) ^ (r & 7)) << 4);

    const int lane = tid & 31, wid = tid >> 5;
    const int wm = wid >> 2, wn = wid & 3;
    const int m_in   = lane & 15;
    const int a_ksel = (lane >> 4) & 1;
    const int n_in   = (lane & 7) + ((lane >> 4) & 1) * 8;
    const int b_ksel = (lane >> 3) & 1;
    const uint32_t a_base = (uint32_t)(wm * 64 + m_in) * 128u;
    const uint32_t b_base = 16384u + (uint32_t)(wn * 32 + n_in) * 128u;
    const uint32_t a_sw = (uint32_t)(m_in & 7);
    const uint32_t b_sw = (uint32_t)(n_in & 7);

    float d[4][4][4];
#pragma unroll
    for (int i = 0; i < 4; i++)
#pragma unroll
        for (int j = 0; j < 4; j++)
#pragma unroll
            for (int q = 0; q < 4; q++) d[i][j][q] = 0.f;

    const int NCH = D_ / KC;  // 32

#pragma unroll
    for (int s = 0; s < NSTAGE - 1; s++) {
        const uint32_t ab = smem_u32 + (uint32_t)s * STAGE_B + st_row;
        const uint16_t* ap = aptr + s * KC;
        const uint16_t* bp = bptr + s * KC;
#pragma unroll
        for (int u = 0; u < 4; u++) CP_ASYNC16(ab + dsw[u], ap + u * 8);
#pragma unroll
        for (int u = 0; u < 4; u++) CP_ASYNC16(ab + 16384u + dsw[u], bp + u * 8);
        CP_COMMIT();
    }

    for (int c = 0; c < NCH; ++c) {
        CP_WAIT2();
        __syncthreads();

        const int nc = c + NSTAGE - 1;
        if (nc < NCH) {
            const uint32_t ab = smem_u32 + (uint32_t)(nc & (NSTAGE - 1)) * STAGE_B + st_row;
            const uint16_t* ap = aptr + nc * KC;
            const uint16_t* bp = bptr + nc * KC;
#pragma unroll
            for (int u = 0; u < 4; u++) CP_ASYNC16(ab + dsw[u], ap + u * 8);
#pragma unroll
            for (int u = 0; u < 4; u++) CP_ASYNC16(ab + 16384u + dsw[u], bp + u * 8);
        }
        CP_COMMIT();

        const uint32_t st = smem_u32 + (uint32_t)(c & (NSTAGE - 1)) * STAGE_B;
        const uint32_t abase = st + a_base;
        const uint32_t bbase = st + b_base;

        uint32_t af[2][4][4], bf[2][2][4];
        {
            const uint32_t ka = (uint32_t)((a_ksel ^ a_sw) << 4);
            const uint32_t kb = (uint32_t)((b_ksel ^ b_sw) << 4);
#pragma unroll
            for (int mi = 0; mi < 4; mi++) LDSM_X4(af[0][mi], abase + mi * 2048 + ka);
#pragma unroll
            for (int np = 0; np < 2; np++) LDSM_X4(bf[0][np], bbase + np * 2048 + kb);
        }
#pragma unroll
        for (int s = 0; s < 4; ++s) {
            const int cur = s & 1, nxt = cur ^ 1;
            if (s < 3) {
                const uint32_t ka = (uint32_t)(((2 * (s + 1) + a_ksel) ^ a_sw) << 4);
                const uint32_t kb = (uint32_t)(((2 * (s + 1) + b_ksel) ^ b_sw) << 4);
#pragma unroll
                for (int mi = 0; mi < 4; mi++) LDSM_X4(af[nxt][mi], abase + mi * 2048 + ka);
#pragma unroll
                for (int np = 0; np < 2; np++) LDSM_X4(bf[nxt][np], bbase + np * 2048 + kb);
            }
#pragma unroll
            for (int mi = 0; mi < 4; mi++) {
                MMA_BF16(d[mi][0], af[cur][mi], bf[cur][0][0], bf[cur][0][1]);
                MMA_BF16(d[mi][1], af[cur][mi], bf[cur][0][2], bf[cur][0][3]);
                MMA_BF16(d[mi][2], af[cur][mi], bf[cur][1][0], bf[cur][1][1]);
                MMA_BF16(d[mi][3], af[cur][mi], bf[cur][1][2], bf[cur][1][3]);
            }
        }
    }

    const int g = lane >> 2, t = lane & 3;
#pragma unroll
    for (int mi = 0; mi < 4; mi++) {
        const int r0 = mtile * 128 + wm * 64 + mi * 16 + g;
        const int r1 = r0 + 8;
        const float qn0 = g_qnt[r0], qn1 = g_qnt[r1];
        uint16_t* o0 = g_key + (size_t)r0 * NTOT;
        uint16_t* o1 = g_key + (size_t)r1 * NTOT;
#pragma unroll
        for (int ni = 0; ni < 4; ni++) {
            const int c0 = ntile * 128 + wn * 32 + ni * 8 + 2 * t;
            const float gn0 = g_gn[c0], gn1 = g_gn[c0 + 1];
            float v00 = qn0 + gn0 - 2.f * d[mi][ni][0];
            float v01 = qn0 + gn1 - 2.f * d[mi][ni][1];
            float v10 = qn1 + gn0 - 2.f * d[mi][ni][2];
            float v11 = qn1 + gn1 - 2.f * d[mi][ni][3];
            int k00 = (int)(__float_as_uint(fmaxf(v00, EPS_F)) >> 12) - KEY_OFF;
            int k01 = (int)(__float_as_uint(fmaxf(v01, EPS_F)) >> 12) - KEY_OFF;
            int k10 = (int)(__float_as_uint(fmaxf(v10, EPS_F)) >> 12) - KEY_OFF;
            int k11 = (int)(__float_as_uint(fmaxf(v11, EPS_F)) >> 12) - KEY_OFF;
            k00 = min(max(k00, 0), 65535); k01 = min(max(k01, 0), 65535);
            k10 = min(max(k10, 0), 65535); k11 = min(max(k11, 0), 65535);
            *(uint32_t*)(o0 + c0) = (uint32_t)k00 | ((uint32_t)k01 << 16);
            *(uint32_t*)(o1 + c0) = (uint32_t)k10 | ((uint32_t)k11 << 16);
        }
    }
}

// ---------------- kernel 3: candidate selection (split, light) ----------------
__global__ void __launch_bounds__(256) select_kernel() {
    const int b = blockIdx.x;
    const int tid = threadIdx.x;
    __shared__ unsigned hist[4096];
    __shared__ int s_bin;
    __shared__ unsigned candCnt;

    const uint16_t* row = g_key + (size_t)b * NTOT;
    for (int i = tid; i < 4096; i += 256) hist[i] = 0;
    if (tid == 0) candCnt = 0;
    __syncthreads();

    const uint4* row4 = (const uint4*)row;
#pragma unroll
    for (int u = 0; u < 4; u++) {
        uint4 v = row4[tid + u * 256];
        const uint32_t w[4] = {v.x, v.y, v.z, v.w};
#pragma unroll
        for (int j = 0; j < 4; j++) {
            atomicAdd(&hist[min(w[j] & 0xFFFFu, 4095u)], 1u);
            atomicAdd(&hist[min(w[j] >> 16, 4095u)], 1u);
        }
    }
    __syncthreads();

    {
        unsigned cnts[16], local = 0;
#pragma unroll
        for (int c = 0; c < 16; c++) { cnts[c] = hist[tid * 16 + c]; local += cnts[c]; }
        unsigned inc = local;
        const int lane = tid & 31, wid = tid >> 5;
#pragma unroll
        for (int off = 1; off < 32; off <<= 1) {
            unsigned n = __shfl_up_sync(0xffffffffu, inc, off);
            if (lane >= off) inc += n;
        }
        __shared__ unsigned wsum[8];
        if (lane == 31) wsum[wid] = inc;
        __syncthreads();
        if (tid == 0) {
            unsigned run = 0;
            for (int w = 0; w < 8; w++) { unsigned t = wsum[w]; wsum[w] = run; run += t; }
        }
        __syncthreads();
        unsigned excl = inc - local + wsum[wid];
        if (excl < NSEL && NSEL <= excl + local) {
            unsigned run = excl;
            for (int c = 0; c < 16; c++) {
                run += cnts[c];
                if (run >= NSEL) { s_bin = tid * 16 + c; break; }
            }
        }
        __syncthreads();
    }

    const unsigned thr = (unsigned)s_bin;
#pragma unroll
    for (int u = 0; u < 4; u++) {
        uint4 v = row4[tid + u * 256];
        const uint32_t w[4] = {v.x, v.y, v.z, v.w};
        const int base = (tid + u * 256) * 8;
#pragma unroll
        for (int j = 0; j < 4; j++) {
            if ((w[j] & 0xFFFFu) <= thr) {
                unsigned pos = atomicAdd(&candCnt, 1u);
                if (pos < CAND_MAX) g_cand[b * CAND_MAX + pos] = base + j * 2;
            }
            if ((w[j] >> 16) <= thr) {
                unsigned pos = atomicAdd(&candCnt, 1u);
                if (pos < CAND_MAX) g_cand[b * CAND_MAX + pos] = base + j * 2 + 1;
            }
        }
    }
    __syncthreads();
    if (tid == 0) g_candn[b] = (int)min(candCnt, (unsigned)CAND_MAX);
}

// ---------------- kernel 4: fp32 recompute (bf16 gallery) + topK + rank loss --
// Round-14: dual accumulator chains per dot (j-parity split) to halve the FMA
// dependency latency; student squares computed inline from f_s (bit-identical
// to the old g_fsq values).
__global__ void __launch_bounds__(256, 2) stfuse_kernel(const float* __restrict__ f_s) {
    const int b = blockIdx.x;
    const int tid = threadIdx.x;
    const int lane = tid & 31, wid = tid >> 5;

    __shared__ __align__(16) float qs[D_];
    __shared__ __align__(16) float qt[D_];
    __shared__ int   s_idx[CAND_MAX];
    __shared__ float s_sd2[CAND_MAX];
    __shared__ unsigned long long s_key[CAND_MAX];
    __shared__ float tv[KSEL], sv[KSEL];

    const int C = g_candn[b];
    {
        const float4* ps = (const float4*)(f_s + (size_t)b * D_);
        const float4* pt = (const float4*)(g_ftq + (size_t)b * D_);
#pragma unroll
        for (int u = 0; u < 2; u++) {
            float4 v = ps[tid + u * 256];
            ((float4*)qs)[tid + u * 256] =
                make_float4(v.x * v.x, v.y * v.y, v.z * v.z, v.w * v.w);
            ((float4*)qt)[tid + u * 256] = pt[tid + u * 256];
        }
        if (tid < CAND_MAX) {
            s_idx[tid] = (tid < C) ? g_cand[b * CAND_MAX + tid] : 0;
            s_key[tid] = 0xFFFFFFFFFFFFFFFFULL;
        }
    }
    __syncthreads();

    const float qns = g_qns[b], qnt = g_qnt[b];
    const float selfd2 = g_selfd2[b];

    // 8 warps; both dots per candidate; all 8 gallery loads up front (MLP=8);
    // dual accumulator chains (j parity) for 4 independent FMA chains.
    for (int kk = wid; kk < C; kk += 8) {
        const int id = s_idx[kk];
        const uint4* g4 = (id < N0_) ? (const uint4*)(g_gal_bf + (size_t)id * D_)
                                     : (const uint4*)(g_ftq_bf + (size_t)(id - N0_) * D_);
        uint4 v[8];
#pragma unroll
        for (int j = 0; j < 8; j++) v[j] = g4[lane + 32 * j];

        float ds0 = 0.f, ds1 = 0.f, dt0 = 0.f, dt1 = 0.f;
#pragma unroll
        for (int j = 0; j < 8; j++) {
            const int i = lane + 32 * j;
            float2 g0 = __bfloat1622float2(*(const __nv_bfloat162*)&v[j].x);
            float2 g1 = __bfloat1622float2(*(const __nv_bfloat162*)&v[j].y);
            float2 g2 = __bfloat1622float2(*(const __nv_bfloat162*)&v[j].z);
            float2 g3 = __bfloat1622float2(*(const __nv_bfloat162*)&v[j].w);
            float4 a0 = ((const float4*)qs)[2 * i], a1 = ((const float4*)qs)[2 * i + 1];
            float4 t0 = ((const float4*)qt)[2 * i], t1 = ((const float4*)qt)[2 * i + 1];
            const float dsp = a0.x * g0.x + a0.y * g0.y + a0.z * g1.x + a0.w * g1.y
                            + a1.x * g2.x + a1.y * g2.y + a1.z * g3.x + a1.w * g3.y;
            const float dtp = t0.x * g0.x + t0.y * g0.y + t0.z * g1.x + t0.w * g1.y
                            + t1.x * g2.x + t1.y * g2.y + t1.z * g3.x + t1.w * g3.y;
            if (j & 1) { ds1 += dsp; dt1 += dtp; }
            else       { ds0 += dsp; dt0 += dtp; }
        }
        float ds = ds0 + ds1, dt = dt0 + dt1;
#pragma unroll
        for (int o = 16; o; o >>= 1) {
            ds += __shfl_down_sync(0xffffffffu, ds, o);
            dt += __shfl_down_sync(0xffffffffu, dt, o);
        }
        if (lane == 0) {
            const float gn = g_gn[id];
            s_sd2[kk] = fmaxf(qns + gn - 2.f * ds, EPS_F);
            float td2 = (id == N0_ + b) ? selfd2 : fmaxf(qnt + gn - 2.f * dt, EPS_F);
            s_key[kk] = ((unsigned long long)__float_as_uint(td2) << 32)
                        | ((unsigned)id << 8) | (unsigned)kk;
        }
    }
    __syncthreads();

    // bitonic sort 256 entries ascending (value, index tie-break)
    for (int ksz = 2; ksz <= CAND_MAX; ksz <<= 1) {
        for (int j = ksz >> 1; j > 0; j >>= 1) {
            int ixj = tid ^ j;
            if (ixj > tid) {
                unsigned long long a = s_key[tid], c = s_key[ixj];
                bool up = ((tid & ksz) == 0);
                if ((a > c) == up) { s_key[tid] = c; s_key[ixj] = a; }
            }
            __syncthreads();
        }
    }

    if (tid < KSEL) {
        unsigned long long e = s_key[tid];
        tv[tid] = sqrtf(__uint_as_float((unsigned)(e >> 32)));
        sv[tid] = sqrtf(s_sd2[(unsigned)(e & 0xFFu)]);
    }
    __syncthreads();

    float p = 0.f;
    if (tid >= 1 && tid < KSEL) {
        const float ti = tv[tid], si = sv[tid];
        float tr = 0.f, sr = 0.f;
#pragma unroll 4
        for (int j = 1; j < KSEL; j++) {
            tr += fmaxf(ti - tv[j], 0.f);
            sr += fmaxf(si - sv[j], 0.f);
        }
        const float dd = tr - sr;
        p = dd * dd;
    }
    const float s = blockReduceSum(p);
    if (tid == 0) {
        g_rowextra[b] = sqrtf(s);
        g_rowmain[b]  = fabsf(sv[0] - tv[0]);
    }
}

// ---------------- kernel 5: deterministic final reduction ---------------------
__global__ void __launch_bounds__(256) final_kernel(float* __restrict__ out) {
    __shared__ float sm[256], se[256];
    const int t = threadIdx.x;
    sm[t] = g_rowmain[t];
    se[t] = g_rowextra[t];
    __syncthreads();
    for (int s = 128; s > 0; s >>= 1) {
        if (t < s) { sm[t] += sm[t + s]; se[t] += se[t + s]; }
        __syncthreads();
    }
    if (t == 0) {
        float main_loss  = sm[0] / (float)B_;
        float extra_loss = (se[0] / (float)B_) / (float)(KSEL - 1);
        out[0] = main_loss + extra_loss;
    }
}

// ---------------- launch ------------------------------------------------------
extern "C" void kernel_launch(void* const* d_in, const int* in_sizes, int n_in,
                              void* d_out, int out_size) {
    const float* f_s     = (const float*)d_in[0];
    const float* f_t     = (const float*)d_in[1];
    const float* gallery = (const float*)d_in[2];
    float* out = (float*)d_out;

    cudaFuncSetAttribute(bf16_gemm_kernel, cudaFuncAttributeMaxDynamicSharedMemorySize, GEMM_SMEM);

    prep_kernel<<<B_ + N0_ + B_, 256>>>(f_s, f_t, gallery);
    bf16_gemm_kernel<<<dim3(NTOT / 128, B_ / 128), 256, GEMM_SMEM>>>();
    select_kernel<<<B_, 256>>>();
    stfuse_kernel<<<B_, 256>>>(f_s);
    final_kernel<<<1, 256>>>(out);
}

// round 15
// speedup vs baseline: 1.0162x; 1.0162x over previous
#include <cuda_runtime.h>
#include <cuda_bf16.h>
#include <cstdint>

// Problem constants
#define B_    256
#define D_    2048
#define N0_   7936
#define NTOT  8192
#define KSEL  128
#define NSEL  144          // selection margin: collect >= 144 noisy-smallest
#define CAND_MAX 256
#define EPS_F 1e-12f
#define KEY_OFF 0x45800    // (bits of 4096.0f) >> 12

// ---------------- scratch ----------------------------------------------------
__device__ float    g_ftq[B_ * D_];             // f_t^2 (fp32)
__device__ uint16_t g_ftq_bf[B_ * D_];          // f_t^2 bf16
__device__ uint16_t g_gal_bf[(size_t)N0_ * D_]; // gallery bf16
__device__ float    g_qns[B_];
__device__ float    g_qnt[B_];
__device__ float    g_gn[NTOT];
__device__ float    g_selfd2[B_];               // reference-noise-scale self d2
__device__ uint16_t g_key[(size_t)B_ * NTOT];   // quantized d2 keys
__device__ int      g_cand[B_ * CAND_MAX];
__device__ int      g_candn[B_];
__device__ float    g_rowmain[B_];
__device__ float    g_rowextra[B_];

// ---------------- PTX helpers -------------------------------------------------
__device__ __forceinline__ uint32_t smem_to_u32(const void* p) {
    uint32_t a;
    asm("{ .reg .u64 t; cvta.to.shared.u64 t, %1; cvt.u32.u64 %0, t; }" : "=r"(a) : "l"(p));
    return a;
}

#define LDSM_X4(R, ADDR) \
    asm volatile("ldmatrix.sync.aligned.m8n8.x4.shared.b16 {%0,%1,%2,%3}, [%4];" \
        : "=r"((R)[0]), "=r"((R)[1]), "=r"((R)[2]), "=r"((R)[3]) : "r"(ADDR))

#define MMA_BF16(D, A, B0, B1) \
    asm volatile("mma.sync.aligned.m16n8k16.row.col.f32.bf16.bf16.f32 " \
        "{%0,%1,%2,%3}, {%4,%5,%6,%7}, {%8,%9}, {%0,%1,%2,%3};" \
        : "+f"((D)[0]), "+f"((D)[1]), "+f"((D)[2]), "+f"((D)[3]) \
        : "r"((A)[0]), "r"((A)[1]), "r"((A)[2]), "r"((A)[3]), "r"(B0), "r"(B1))

#define CP_ASYNC16(dst, src) \
    asm volatile("cp.async.cg.shared.global [%0], [%1], 16;" :: "r"(dst), "l"(src))
#define CP_COMMIT() asm volatile("cp.async.commit_group;" ::: "memory")
#define CP_WAIT2()  asm volatile("cp.async.wait_group 2;" ::: "memory")

__device__ __forceinline__ float blockReduceSum(float v) {
    int lane = threadIdx.x & 31, wid = threadIdx.x >> 5;
#pragma unroll
    for (int o = 16; o; o >>= 1) v += __shfl_down_sync(0xffffffffu, v, o);
    __shared__ float sh[32];
    if (lane == 0) sh[wid] = v;
    __syncthreads();
    int nw = (blockDim.x + 31) >> 5;
    v = (threadIdx.x < nw) ? sh[threadIdx.x] : 0.f;
    if (wid == 0) {
#pragma unroll
        for (int o = 16; o; o >>= 1) v += __shfl_down_sync(0xffffffffu, v, o);
    }
    return v;
}

__device__ __forceinline__ uint32_t pack_bf2(float a, float b) {
    return (uint32_t)__bfloat16_as_ushort(__float2bfloat16(a)) |
           ((uint32_t)__bfloat16_as_ushort(__float2bfloat16(b)) << 16);
}

// ---------------- kernel 1: unified prep --------------------------------------
__global__ void __launch_bounds__(256) prep_kernel(const float* __restrict__ f_s,
                                                   const float* __restrict__ f_t,
                                                   const float* __restrict__ gallery) {
    __shared__ __align__(16) float row[D_];
    const int bid = blockIdx.x;
    const int tid = threadIdx.x;

    if (bid < B_) {
        // ---- teacher row ----
        const float4* src = (const float4*)(f_t + (size_t)bid * D_);
        float4* dst = (float4*)(g_ftq + (size_t)bid * D_);
        uint4* dbf = (uint4*)(g_ftq_bf + (size_t)bid * D_);
        const int i = tid * 2;
        float4 v0 = src[i], v1 = src[i + 1];
        float4 s0 = make_float4(v0.x * v0.x, v0.y * v0.y, v0.z * v0.z, v0.w * v0.w);
        float4 s1 = make_float4(v1.x * v1.x, v1.y * v1.y, v1.z * v1.z, v1.w * v1.w);
        dst[i] = s0; dst[i + 1] = s1;
        ((float4*)row)[i] = s0; ((float4*)row)[i + 1] = s1;
        uint4 bf;
        bf.x = pack_bf2(s0.x, s0.y); bf.y = pack_bf2(s0.z, s0.w);
        bf.z = pack_bf2(s1.x, s1.y); bf.w = pack_bf2(s1.z, s1.w);
        dbf[tid] = bf;

        // qnt: sq order
        float p = 0.f;
        p += s0.x * s0.x + s0.y * s0.y + s0.z * s0.z + s0.w * s0.w;
        p += s1.x * s1.x + s1.y * s1.y + s1.z * s1.z + s1.w * s1.w;
        const float qnt_tot = blockReduceSum(p);
        if (tid == 0) g_qnt[bid] = qnt_tot;
        __syncthreads();

        // gn: galnorm order
        float pg = 0.f;
#pragma unroll
        for (int u = 0; u < 2; u++) {
            float4 s = ((const float4*)row)[tid + u * 256];
            pg += s.x * s.x + s.y * s.y + s.z * s.z + s.w * s.w;
        }
        const float gn_tot = blockReduceSum(pg);
        if (tid == 0) {
            g_gn[N0_ + bid] = gn_tot;
            // PURE SEQUENTIAL fp32 FMA chain (reference-noise-scale selfd2)
            float acc = 0.f;
#pragma unroll 16
            for (int k = 0; k < D_; k++) acc = fmaf(row[k], row[k], acc);
            const float t = qnt_tot + gn_tot;
            g_selfd2[bid] = fmaxf(fmaf(-2.f, acc, t), EPS_F);
        }
    } else if (bid < B_ + N0_) {
        // ---- gallery row ----
        const int n = bid - B_;
        const float4* g = (const float4*)(gallery + (size_t)n * D_);
        uint4* dbf = (uint4*)(g_gal_bf + (size_t)n * D_);
        float p = 0.f;
        float4 v0 = g[tid * 2], v1 = g[tid * 2 + 1];
        p += v0.x * v0.x + v0.y * v0.y + v0.z * v0.z + v0.w * v0.w;
        p += v1.x * v1.x + v1.y * v1.y + v1.z * v1.z + v1.w * v1.w;
        uint4 bf;
        bf.x = pack_bf2(v0.x, v0.y); bf.y = pack_bf2(v0.z, v0.w);
        bf.z = pack_bf2(v1.x, v1.y); bf.w = pack_bf2(v1.z, v1.w);
        dbf[tid] = bf;
        float tot = blockReduceSum(p);
        if (tid == 0) g_gn[n] = tot;
    } else {
        // ---- student row: qns only ----
        const int r = bid - B_ - N0_;
        const float4* src = (const float4*)(f_s + (size_t)r * D_);
        float p = 0.f;
#pragma unroll
        for (int u = 0; u < 2; u++) {
            float4 v = src[tid + u * 256];
            float4 s = make_float4(v.x * v.x, v.y * v.y, v.z * v.z, v.w * v.w);
            p += s.x * s.x + s.y * s.y + s.z * s.z + s.w * s.w;
        }
        float tot = blockReduceSum(p);
        if (tid == 0) g_qns[r] = tot;
    }
}

// ---------------- kernel 2: bf16 mma.sync GEMM -> quantized keys --------------
#define KC 64
#define NSTAGE 4
#define STAGE_B 32768
#define GEMM_SMEM (NSTAGE * STAGE_B)

__global__ void __launch_bounds__(256) bf16_gemm_kernel() {
    extern __shared__ __align__(16) char smem[];
    const int tid = threadIdx.x;
    const int ntile = blockIdx.x;    // 0..63
    const int mtile = blockIdx.y;    // 0..1

    const int r  = tid >> 1;
    const int h  = tid & 1;
    const uint16_t* aptr = g_ftq_bf + (size_t)(mtile * 128 + r) * D_ + h * 32;
    const int grow = ntile * 128 + r;
    const uint16_t* bptr = ((grow < N0_) ? (g_gal_bf + (size_t)grow * D_)
                                         : (g_ftq_bf + (size_t)(grow - N0_) * D_)) + h * 32;
    const uint32_t smem_u32 = smem_to_u32(smem);
    const uint32_t st_row = (uint32_t)r * 128u;
    uint32_t dsw[4];
#pragma unroll
    for (int u = 0; u < 4; u++) dsw[u] = (uint32_t)(((h * 4 + u) ^ (r & 7)) << 4);

    const int lane = tid & 31, wid = tid >> 5;
    const int wm = wid >> 2, wn = wid & 3;
    const int m_in   = lane & 15;
    const int a_ksel = (lane >> 4) & 1;
    const int n_in   = (lane & 7) + ((lane >> 4) & 1) * 8;
    const int b_ksel = (lane >> 3) & 1;
    const uint32_t a_base = (uint32_t)(wm * 64 + m_in) * 128u;
    const uint32_t b_base = 16384u + (uint32_t)(wn * 32 + n_in) * 128u;
    const uint32_t a_sw = (uint32_t)(m_in & 7);
    const uint32_t b_sw = (uint32_t)(n_in & 7);

    float d[4][4][4];
#pragma unroll
    for (int i = 0; i < 4; i++)
#pragma unroll
        for (int j = 0; j < 4; j++)
#pragma unroll
            for (int q = 0; q < 4; q++) d[i][j][q] = 0.f;

    const int NCH = D_ / KC;  // 32

#pragma unroll
    for (int s = 0; s < NSTAGE - 1; s++) {
        const uint32_t ab = smem_u32 + (uint32_t)s * STAGE_B + st_row;
        const uint16_t* ap = aptr + s * KC;
        const uint16_t* bp = bptr + s * KC;
#pragma unroll
        for (int u = 0; u < 4; u++) CP_ASYNC16(ab + dsw[u], ap + u * 8);
#pragma unroll
        for (int u = 0; u < 4; u++) CP_ASYNC16(ab + 16384u + dsw[u], bp + u * 8);
        CP_COMMIT();
    }

    for (int c = 0; c < NCH; ++c) {
        CP_WAIT2();
        __syncthreads();

        const int nc = c + NSTAGE - 1;
        if (nc < NCH) {
            const uint32_t ab = smem_u32 + (uint32_t)(nc & (NSTAGE - 1)) * STAGE_B + st_row;
            const uint16_t* ap = aptr + nc * KC;
            const uint16_t* bp = bptr + nc * KC;
#pragma unroll
            for (int u = 0; u < 4; u++) CP_ASYNC16(ab + dsw[u], ap + u * 8);
#pragma unroll
            for (int u = 0; u < 4; u++) CP_ASYNC16(ab + 16384u + dsw[u], bp + u * 8);
        }
        CP_COMMIT();

        const uint32_t st = smem_u32 + (uint32_t)(c & (NSTAGE - 1)) * STAGE_B;
        const uint32_t abase = st + a_base;
        const uint32_t bbase = st + b_base;

        uint32_t af[2][4][4], bf[2][2][4];
        {
            const uint32_t ka = (uint32_t)((a_ksel ^ a_sw) << 4);
            const uint32_t kb = (uint32_t)((b_ksel ^ b_sw) << 4);
#pragma unroll
            for (int mi = 0; mi < 4; mi++) LDSM_X4(af[0][mi], abase + mi * 2048 + ka);
#pragma unroll
            for (int np = 0; np < 2; np++) LDSM_X4(bf[0][np], bbase + np * 2048 + kb);
        }
#pragma unroll
        for (int s = 0; s < 4; ++s) {
            const int cur = s & 1, nxt = cur ^ 1;
            if (s < 3) {
                const uint32_t ka = (uint32_t)(((2 * (s + 1) + a_ksel) ^ a_sw) << 4);
                const uint32_t kb = (uint32_t)(((2 * (s + 1) + b_ksel) ^ b_sw) << 4);
#pragma unroll
                for (int mi = 0; mi < 4; mi++) LDSM_X4(af[nxt][mi], abase + mi * 2048 + ka);
#pragma unroll
                for (int np = 0; np < 2; np++) LDSM_X4(bf[nxt][np], bbase + np * 2048 + kb);
            }
#pragma unroll
            for (int mi = 0; mi < 4; mi++) {
                MMA_BF16(d[mi][0], af[cur][mi], bf[cur][0][0], bf[cur][0][1]);
                MMA_BF16(d[mi][1], af[cur][mi], bf[cur][0][2], bf[cur][0][3]);
                MMA_BF16(d[mi][2], af[cur][mi], bf[cur][1][0], bf[cur][1][1]);
                MMA_BF16(d[mi][3], af[cur][mi], bf[cur][1][2], bf[cur][1][3]);
            }
        }
    }

    const int g = lane >> 2, t = lane & 3;
#pragma unroll
    for (int mi = 0; mi < 4; mi++) {
        const int r0 = mtile * 128 + wm * 64 + mi * 16 + g;
        const int r1 = r0 + 8;
        const float qn0 = g_qnt[r0], qn1 = g_qnt[r1];
        uint16_t* o0 = g_key + (size_t)r0 * NTOT;
        uint16_t* o1 = g_key + (size_t)r1 * NTOT;
#pragma unroll
        for (int ni = 0; ni < 4; ni++) {
            const int c0 = ntile * 128 + wn * 32 + ni * 8 + 2 * t;
            const float gn0 = g_gn[c0], gn1 = g_gn[c0 + 1];
            float v00 = qn0 + gn0 - 2.f * d[mi][ni][0];
            float v01 = qn0 + gn1 - 2.f * d[mi][ni][1];
            float v10 = qn1 + gn0 - 2.f * d[mi][ni][2];
            float v11 = qn1 + gn1 - 2.f * d[mi][ni][3];
            int k00 = (int)(__float_as_uint(fmaxf(v00, EPS_F)) >> 12) - KEY_OFF;
            int k01 = (int)(__float_as_uint(fmaxf(v01, EPS_F)) >> 12) - KEY_OFF;
            int k10 = (int)(__float_as_uint(fmaxf(v10, EPS_F)) >> 12) - KEY_OFF;
            int k11 = (int)(__float_as_uint(fmaxf(v11, EPS_F)) >> 12) - KEY_OFF;
            k00 = min(max(k00, 0), 65535); k01 = min(max(k01, 0), 65535);
            k10 = min(max(k10, 0), 65535); k11 = min(max(k11, 0), 65535);
            *(uint32_t*)(o0 + c0) = (uint32_t)k00 | ((uint32_t)k01 << 16);
            *(uint32_t*)(o1 + c0) = (uint32_t)k10 | ((uint32_t)k11 << 16);
        }
    }
}

// ---------------- kernel 3: candidate selection (split, light) ----------------
__global__ void __launch_bounds__(256) select_kernel() {
    const int b = blockIdx.x;
    const int tid = threadIdx.x;
    __shared__ unsigned hist[4096];
    __shared__ int s_bin;
    __shared__ unsigned candCnt;

    const uint16_t* row = g_key + (size_t)b * NTOT;
    for (int i = tid; i < 4096; i += 256) hist[i] = 0;
    if (tid == 0) candCnt = 0;
    __syncthreads();

    const uint4* row4 = (const uint4*)row;
#pragma unroll
    for (int u = 0; u < 4; u++) {
        uint4 v = row4[tid + u * 256];
        const uint32_t w[4] = {v.x, v.y, v.z, v.w};
#pragma unroll
        for (int j = 0; j < 4; j++) {
            atomicAdd(&hist[min(w[j] & 0xFFFFu, 4095u)], 1u);
            atomicAdd(&hist[min(w[j] >> 16, 4095u)], 1u);
        }
    }
    __syncthreads();

    {
        unsigned cnts[16], local = 0;
#pragma unroll
        for (int c = 0; c < 16; c++) { cnts[c] = hist[tid * 16 + c]; local += cnts[c]; }
        unsigned inc = local;
        const int lane = tid & 31, wid = tid >> 5;
#pragma unroll
        for (int off = 1; off < 32; off <<= 1) {
            unsigned n = __shfl_up_sync(0xffffffffu, inc, off);
            if (lane >= off) inc += n;
        }
        __shared__ unsigned wsum[8];
        if (lane == 31) wsum[wid] = inc;
        __syncthreads();
        if (tid == 0) {
            unsigned run = 0;
            for (int w = 0; w < 8; w++) { unsigned t = wsum[w]; wsum[w] = run; run += t; }
        }
        __syncthreads();
        unsigned excl = inc - local + wsum[wid];
        if (excl < NSEL && NSEL <= excl + local) {
            unsigned run = excl;
            for (int c = 0; c < 16; c++) {
                run += cnts[c];
                if (run >= NSEL) { s_bin = tid * 16 + c; break; }
            }
        }
        __syncthreads();
    }

    const unsigned thr = (unsigned)s_bin;
#pragma unroll
    for (int u = 0; u < 4; u++) {
        uint4 v = row4[tid + u * 256];
        const uint32_t w[4] = {v.x, v.y, v.z, v.w};
        const int base = (tid + u * 256) * 8;
#pragma unroll
        for (int j = 0; j < 4; j++) {
            if ((w[j] & 0xFFFFu) <= thr) {
                unsigned pos = atomicAdd(&candCnt, 1u);
                if (pos < CAND_MAX) g_cand[b * CAND_MAX + pos] = base + j * 2;
            }
            if ((w[j] >> 16) <= thr) {
                unsigned pos = atomicAdd(&candCnt, 1u);
                if (pos < CAND_MAX) g_cand[b * CAND_MAX + pos] = base + j * 2 + 1;
            }
        }
    }
    __syncthreads();
    if (tid == 0) g_candn[b] = (int)min(candCnt, (unsigned)CAND_MAX);
}

// ---------------- kernel 4: fp32 recompute + topK + rank loss -----------------
// Round-15: each warp processes TWO candidates per pass, reading each qs/qt
// float4 from smem ONCE and feeding both accumulations (halves the LDS
// traffic that bound round 13/14). Per-candidate arithmetic is round-13's
// exact single-chain expression -> keys bit-identical.
__global__ void __launch_bounds__(256, 2) stfuse_kernel(const float* __restrict__ f_s) {
    const int b = blockIdx.x;
    const int tid = threadIdx.x;
    const int lane = tid & 31, wid = tid >> 5;

    __shared__ __align__(16) float qs[D_];
    __shared__ __align__(16) float qt[D_];
    __shared__ int   s_idx[CAND_MAX];
    __shared__ float s_sd2[CAND_MAX];
    __shared__ unsigned long long s_key[CAND_MAX];
    __shared__ float tv[KSEL], sv[KSEL];

    const int C = g_candn[b];
    {
        const float4* ps = (const float4*)(f_s + (size_t)b * D_);
        const float4* pt = (const float4*)(g_ftq + (size_t)b * D_);
#pragma unroll
        for (int u = 0; u < 2; u++) {
            float4 v = ps[tid + u * 256];
            ((float4*)qs)[tid + u * 256] =
                make_float4(v.x * v.x, v.y * v.y, v.z * v.z, v.w * v.w);
            ((float4*)qt)[tid + u * 256] = pt[tid + u * 256];
        }
        if (tid < CAND_MAX) {
            s_idx[tid] = (tid < C) ? g_cand[b * CAND_MAX + tid] : 0;
            s_key[tid] = 0xFFFFFFFFFFFFFFFFULL;
        }
    }
    __syncthreads();

    const float qns = g_qns[b], qnt = g_qnt[b];
    const float selfd2 = g_selfd2[b];

    // 8 warps x 2 candidates per pass
    for (int kk = wid * 2; kk < C; kk += 16) {
        const bool has1 = (kk + 1 < C);
        const int id0 = s_idx[kk];
        const int id1 = has1 ? s_idx[kk + 1] : id0;
        const uint4* ga = (id0 < N0_) ? (const uint4*)(g_gal_bf + (size_t)id0 * D_)
                                      : (const uint4*)(g_ftq_bf + (size_t)(id0 - N0_) * D_);
        const uint4* gb = (id1 < N0_) ? (const uint4*)(g_gal_bf + (size_t)id1 * D_)
                                      : (const uint4*)(g_ftq_bf + (size_t)(id1 - N0_) * D_);
        uint4 va[8], vb[8];
#pragma unroll
        for (int j = 0; j < 8; j++) { va[j] = ga[lane + 32 * j]; vb[j] = gb[lane + 32 * j]; }

        float dsA = 0.f, dtA = 0.f, dsB = 0.f, dtB = 0.f;
#pragma unroll
        for (int j = 0; j < 8; j++) {
            const int i = lane + 32 * j;
            float4 a0 = ((const float4*)qs)[2 * i], a1 = ((const float4*)qs)[2 * i + 1];
            float4 t0 = ((const float4*)qt)[2 * i], t1 = ((const float4*)qt)[2 * i + 1];
            {
                float2 g0 = __bfloat1622float2(*(const __nv_bfloat162*)&va[j].x);
                float2 g1 = __bfloat1622float2(*(const __nv_bfloat162*)&va[j].y);
                float2 g2 = __bfloat1622float2(*(const __nv_bfloat162*)&va[j].z);
                float2 g3 = __bfloat1622float2(*(const __nv_bfloat162*)&va[j].w);
                dsA += a0.x * g0.x + a0.y * g0.y + a0.z * g1.x + a0.w * g1.y
                     + a1.x * g2.x + a1.y * g2.y + a1.z * g3.x + a1.w * g3.y;
                dtA += t0.x * g0.x + t0.y * g0.y + t0.z * g1.x + t0.w * g1.y
                     + t1.x * g2.x + t1.y * g2.y + t1.z * g3.x + t1.w * g3.y;
            }
            {
                float2 g0 = __bfloat1622float2(*(const __nv_bfloat162*)&vb[j].x);
                float2 g1 = __bfloat1622float2(*(const __nv_bfloat162*)&vb[j].y);
                float2 g2 = __bfloat1622float2(*(const __nv_bfloat162*)&vb[j].z);
                float2 g3 = __bfloat1622float2(*(const __nv_bfloat162*)&vb[j].w);
                dsB += a0.x * g0.x + a0.y * g0.y + a0.z * g1.x + a0.w * g1.y
                     + a1.x * g2.x + a1.y * g2.y + a1.z * g3.x + a1.w * g3.y;
                dtB += t0.x * g0.x + t0.y * g0.y + t0.z * g1.x + t0.w * g1.y
                     + t1.x * g2.x + t1.y * g2.y + t1.z * g3.x + t1.w * g3.y;
            }
        }
#pragma unroll
        for (int o = 16; o; o >>= 1) {
            dsA += __shfl_down_sync(0xffffffffu, dsA, o);
            dtA += __shfl_down_sync(0xffffffffu, dtA, o);
            dsB += __shfl_down_sync(0xffffffffu, dsB, o);
            dtB += __shfl_down_sync(0xffffffffu, dtB, o);
        }
        if (lane == 0) {
            {
                const float gn = g_gn[id0];
                s_sd2[kk] = fmaxf(qns + gn - 2.f * dsA, EPS_F);
                float td2 = (id0 == N0_ + b) ? selfd2 : fmaxf(qnt + gn - 2.f * dtA, EPS_F);
                s_key[kk] = ((unsigned long long)__float_as_uint(td2) << 32)
                            | ((unsigned)id0 << 8) | (unsigned)kk;
            }
            if (has1) {
                const float gn = g_gn[id1];
                s_sd2[kk + 1] = fmaxf(qns + gn - 2.f * dsB, EPS_F);
                float td2 = (id1 == N0_ + b) ? selfd2 : fmaxf(qnt + gn - 2.f * dtB, EPS_F);
                s_key[kk + 1] = ((unsigned long long)__float_as_uint(td2) << 32)
                                | ((unsigned)id1 << 8) | (unsigned)(kk + 1);
            }
        }
    }
    __syncthreads();

    // bitonic sort 256 entries ascending (value, index tie-break)
    for (int ksz = 2; ksz <= CAND_MAX; ksz <<= 1) {
        for (int j = ksz >> 1; j > 0; j >>= 1) {
            int ixj = tid ^ j;
            if (ixj > tid) {
                unsigned long long a = s_key[tid], c = s_key[ixj];
                bool up = ((tid & ksz) == 0);
                if ((a > c) == up) { s_key[tid] = c; s_key[ixj] = a; }
            }
            __syncthreads();
        }
    }

    if (tid < KSEL) {
        unsigned long long e = s_key[tid];
        tv[tid] = sqrtf(__uint_as_float((unsigned)(e >> 32)));
        sv[tid] = sqrtf(s_sd2[(unsigned)(e & 0xFFu)]);
    }
    __syncthreads();

    float p = 0.f;
    if (tid >= 1 && tid < KSEL) {
        const float ti = tv[tid], si = sv[tid];
        float tr = 0.f, sr = 0.f;
#pragma unroll 4
        for (int j = 1; j < KSEL; j++) {
            tr += fmaxf(ti - tv[j], 0.f);
            sr += fmaxf(si - sv[j], 0.f);
        }
        const float dd = tr - sr;
        p = dd * dd;
    }
    const float s = blockReduceSum(p);
    if (tid == 0) {
        g_rowextra[b] = sqrtf(s);
        g_rowmain[b]  = fabsf(sv[0] - tv[0]);
    }
}

// ---------------- kernel 5: deterministic final reduction ---------------------
__global__ void __launch_bounds__(256) final_kernel(float* __restrict__ out) {
    __shared__ float sm[256], se[256];
    const int t = threadIdx.x;
    sm[t] = g_rowmain[t];
    se[t] = g_rowextra[t];
    __syncthreads();
    for (int s = 128; s > 0; s >>= 1) {
        if (t < s) { sm[t] += sm[t + s]; se[t] += se[t + s]; }
        __syncthreads();
    }
    if (t == 0) {
        float main_loss  = sm[0] / (float)B_;
        float extra_loss = (se[0] / (float)B_) / (float)(KSEL - 1);
        out[0] = main_loss + extra_loss;
    }
}

// ---------------- launch ------------------------------------------------------
extern "C" void kernel_launch(void* const* d_in, const int* in_sizes, int n_in,
                              void* d_out, int out_size) {
    const float* f_s     = (const float*)d_in[0];
    const float* f_t     = (const float*)d_in[1];
    const float* gallery = (const float*)d_in[2];
    float* out = (float*)d_out;

    cudaFuncSetAttribute(bf16_gemm_kernel, cudaFuncAttributeMaxDynamicSharedMemorySize, GEMM_SMEM);

    prep_kernel<<<B_ + N0_ + B_, 256>>>(f_s, f_t, gallery);
    bf16_gemm_kernel<<<dim3(NTOT / 128, B_ / 128), 256, GEMM_SMEM>>>();
    select_kernel<<<B_, 256>>>();
    stfuse_kernel<<<B_, 256>>>(f_s);
    final_kernel<<<1, 256>>>(out);
}